// round 1
// baseline (speedup 1.0000x reference)
#include <cuda_runtime.h>
#include <cstdint>

// Problem constants (fixed by the reference)
#define BB 2
#define SS 2048
#define DM 1024
#define NH 16
#define DK 64
#define NROWS (BB * SS)               // 4096
#define OUT_ELEMS (NROWS * DM)        // 4194304
#define ATTN_ELEMS (2LL * 16 * 2048 * 2048)  // 134217728

// 1/TEMP = 64^-0.25 = 2^-1.5
#define INV_TEMP 0.35355339059327373f

// Scratch (device globals: allocation-free)
__device__ __align__(128) float g_qn[NROWS * DM];
__device__ __align__(128) float g_qh[NROWS * DM];
__device__ __align__(128) float g_kh[NROWS * DM];
__device__ __align__(128) float g_vh[NROWS * DM];
__device__ __align__(128) float g_oh[NROWS * DM];

// ---------------------------------------------------------------------------
// LayerNorm over last dim (1024), eps=1e-6. One block per row, 256 threads.
// ---------------------------------------------------------------------------
__global__ void ln_kernel(const float* __restrict__ q,
                          const float* __restrict__ gamma,
                          const float* __restrict__ beta,
                          float* __restrict__ out)
{
    __shared__ float red[16];
    const int row = blockIdx.x;
    const int tid = threadIdx.x;
    const float4 v = reinterpret_cast<const float4*>(q)[row * 256 + tid];
    float s  = v.x + v.y + v.z + v.w;
    float s2 = v.x * v.x + v.y * v.y + v.z * v.z + v.w * v.w;
    #pragma unroll
    for (int o = 16; o > 0; o >>= 1) {
        s  += __shfl_xor_sync(0xffffffffu, s,  o);
        s2 += __shfl_xor_sync(0xffffffffu, s2, o);
    }
    if ((tid & 31) == 0) { red[tid >> 5] = s; red[8 + (tid >> 5)] = s2; }
    __syncthreads();
    if (tid < 32) {
        s  = (tid < 8) ? red[tid]     : 0.0f;
        s2 = (tid < 8) ? red[8 + tid] : 0.0f;
        #pragma unroll
        for (int o = 4; o > 0; o >>= 1) {
            s  += __shfl_xor_sync(0xffffffffu, s,  o);
            s2 += __shfl_xor_sync(0xffffffffu, s2, o);
        }
        if (tid == 0) { red[0] = s; red[8] = s2; }
    }
    __syncthreads();
    const float mu   = red[0] * (1.0f / 1024.0f);
    const float var  = red[8] * (1.0f / 1024.0f) - mu * mu;
    const float rstd = rsqrtf(var + 1e-6f);
    const float4 g  = reinterpret_cast<const float4*>(gamma)[tid];
    const float4 bb = reinterpret_cast<const float4*>(beta)[tid];
    float4 y;
    y.x = (v.x - mu) * rstd * g.x + bb.x;
    y.y = (v.y - mu) * rstd * g.y + bb.y;
    y.z = (v.z - mu) * rstd * g.z + bb.z;
    y.w = (v.w - mu) * rstd * g.w + bb.w;
    reinterpret_cast<float4*>(out)[row * 256 + tid] = y;
}

// ---------------------------------------------------------------------------
// SIMT GEMM: C[M,N] = alpha * A[M,K] @ W[K,N] (+ residual). 128x128x16 tiles,
// 256 threads, 8x8 microtile, float4-vectorized smem traffic.
// M,N multiples of 128; K multiple of 16.
// ---------------------------------------------------------------------------
__global__ __launch_bounds__(256, 2)
void gemm_kernel(const float* __restrict__ A, const float* __restrict__ W,
                 float* __restrict__ C, int M, int N, int K,
                 float alpha, const float* __restrict__ residual)
{
    __shared__ float As[16][128];   // [k][m] transposed
    __shared__ float Ws[16][128];   // [k][n]
    const int tid = threadIdx.x;
    const int tx = tid & 15;
    const int ty = tid >> 4;
    const int bm = blockIdx.y * 128;
    const int bn = blockIdx.x * 128;
    float acc[8][8] = {};

    const int aRow = tid >> 2;            // 0..63 (+64)
    const int aCol = (tid & 3) << 2;      // 0,4,8,12
    const int wRow = tid >> 5;            // 0..7 (+8)
    const int wCol = (tid & 31) << 2;     // 0..124

    for (int k0 = 0; k0 < K; k0 += 16) {
        #pragma unroll
        for (int i = 0; i < 2; i++) {
            const int r = aRow + i * 64;
            const float4 v = *reinterpret_cast<const float4*>(
                &A[(size_t)(bm + r) * K + k0 + aCol]);
            As[aCol + 0][r] = v.x; As[aCol + 1][r] = v.y;
            As[aCol + 2][r] = v.z; As[aCol + 3][r] = v.w;
        }
        #pragma unroll
        for (int i = 0; i < 2; i++) {
            const int r = wRow + i * 8;
            *reinterpret_cast<float4*>(&Ws[r][wCol]) =
                *reinterpret_cast<const float4*>(&W[(size_t)(k0 + r) * N + bn + wCol]);
        }
        __syncthreads();
        #pragma unroll
        for (int kk = 0; kk < 16; kk++) {
            float ra[8], rb[8];
            *reinterpret_cast<float4*>(&ra[0]) = *reinterpret_cast<const float4*>(&As[kk][ty * 8]);
            *reinterpret_cast<float4*>(&ra[4]) = *reinterpret_cast<const float4*>(&As[kk][ty * 8 + 4]);
            *reinterpret_cast<float4*>(&rb[0]) = *reinterpret_cast<const float4*>(&Ws[kk][tx * 8]);
            *reinterpret_cast<float4*>(&rb[4]) = *reinterpret_cast<const float4*>(&Ws[kk][tx * 8 + 4]);
            #pragma unroll
            for (int i = 0; i < 8; i++)
                #pragma unroll
                for (int j = 0; j < 8; j++)
                    acc[i][j] += ra[i] * rb[j];
        }
        __syncthreads();
    }

    #pragma unroll
    for (int i = 0; i < 8; i++) {
        const int row = bm + ty * 8 + i;
        #pragma unroll
        for (int j = 0; j < 8; j += 4) {
            const int col = bn + tx * 8 + j;
            const size_t idx = (size_t)row * N + col;
            float4 r4;
            r4.x = acc[i][j + 0] * alpha;
            r4.y = acc[i][j + 1] * alpha;
            r4.z = acc[i][j + 2] * alpha;
            r4.w = acc[i][j + 3] * alpha;
            if (residual) {
                const float4 q4 = *reinterpret_cast<const float4*>(&residual[idx]);
                r4.x += q4.x; r4.y += q4.y; r4.z += q4.z; r4.w += q4.w;
            }
            *reinterpret_cast<float4*>(&C[idx]) = r4;
        }
    }
}

// ---------------------------------------------------------------------------
// Fused attention (no softmax): per (b,h,q-tile of 64):
//   S = Qs @ Ks^T (d=64); mask; write attn tile to gmem; O += S @ Vs.
// 256 threads, 4x4 microtiles over 64x64 tiles. 69.6 KB dynamic smem.
// ---------------------------------------------------------------------------
#define PADW 68
#define ATTN_SMEM (4 * 64 * PADW * (int)sizeof(float))

__global__ __launch_bounds__(256, 2)
void attn_kernel(const float* __restrict__ qh, const float* __restrict__ kh,
                 const float* __restrict__ vh, const int* __restrict__ mask,
                 float* __restrict__ attn_out, float* __restrict__ oh)
{
    extern __shared__ float smem[];
    float (*Qs)[PADW] = reinterpret_cast<float(*)[PADW]>(smem);
    float (*Ks)[PADW] = reinterpret_cast<float(*)[PADW]>(smem + 64 * PADW);
    float (*Vs)[PADW] = reinterpret_cast<float(*)[PADW]>(smem + 2 * 64 * PADW);
    float (*Sm)[PADW] = reinterpret_cast<float(*)[PADW]>(smem + 3 * 64 * PADW);

    const int tid = threadIdx.x;
    const int tx = tid & 15;
    const int ty = tid >> 4;
    const int q0 = blockIdx.x * 64;
    const int bh = blockIdx.y;            // b*NH + h
    const int b  = bh >> 4;
    const int h  = bh & 15;
    const size_t head_off = (size_t)h * DK;

    // Load Q tile (64 rows x 64 cols), 4 float4 per thread
    #pragma unroll
    for (int i = 0; i < 4; i++) {
        const int idx = tid + i * 256;    // float4 index within tile
        const int r = idx >> 4;
        const int c = (idx & 15) << 2;
        *reinterpret_cast<float4*>(&Qs[r][c]) = *reinterpret_cast<const float4*>(
            &qh[(size_t)(b * SS + q0 + r) * DM + head_off + c]);
    }

    float4 o[4];
    #pragma unroll
    for (int i = 0; i < 4; i++) o[i] = make_float4(0.f, 0.f, 0.f, 0.f);

    for (int k0 = 0; k0 < SS; k0 += 64) {
        __syncthreads();
        #pragma unroll
        for (int i = 0; i < 4; i++) {
            const int idx = tid + i * 256;
            const int r = idx >> 4;
            const int c = (idx & 15) << 2;
            const size_t g = (size_t)(b * SS + k0 + r) * DM + head_off + c;
            *reinterpret_cast<float4*>(&Ks[r][c]) = *reinterpret_cast<const float4*>(&kh[g]);
            *reinterpret_cast<float4*>(&Vs[r][c]) = *reinterpret_cast<const float4*>(&vh[g]);
        }
        __syncthreads();

        // S = Q @ K^T over d=64 (Q already scaled by 1/TEMP)
        float s[4][4] = {};
        #pragma unroll
        for (int d = 0; d < 64; d += 4) {
            float4 qv[4], kv[4];
            #pragma unroll
            for (int i = 0; i < 4; i++) qv[i] = *reinterpret_cast<const float4*>(&Qs[ty * 4 + i][d]);
            #pragma unroll
            for (int j = 0; j < 4; j++) kv[j] = *reinterpret_cast<const float4*>(&Ks[tx * 4 + j][d]);
            #pragma unroll
            for (int i = 0; i < 4; i++)
                #pragma unroll
                for (int j = 0; j < 4; j++)
                    s[i][j] += qv[i].x * kv[j].x + qv[i].y * kv[j].y
                             + qv[i].z * kv[j].z + qv[i].w * kv[j].w;
        }

        // Mask + stage to smem + write attn output tile
        #pragma unroll
        for (int i = 0; i < 4; i++) {
            const int row = q0 + ty * 4 + i;
            const int4 mv = *reinterpret_cast<const int4*>(
                &mask[((size_t)b * SS + row) * SS + k0 + tx * 4]);
            float4 sv;
            sv.x = (mv.x == 0) ? -1e9f : s[i][0];
            sv.y = (mv.y == 0) ? -1e9f : s[i][1];
            sv.z = (mv.z == 0) ? -1e9f : s[i][2];
            sv.w = (mv.w == 0) ? -1e9f : s[i][3];
            *reinterpret_cast<float4*>(&Sm[ty * 4 + i][tx * 4]) = sv;
            if (attn_out)
                *reinterpret_cast<float4*>(
                    &attn_out[((size_t)bh * SS + row) * SS + k0 + tx * 4]) = sv;
        }
        __syncthreads();

        // O += S @ V over this 64-chunk
        #pragma unroll 8
        for (int c = 0; c < 64; c++) {
            const float4 vv = *reinterpret_cast<const float4*>(&Vs[c][tx * 4]);
            #pragma unroll
            for (int i = 0; i < 4; i++) {
                const float sc = Sm[ty * 4 + i][c];
                o[i].x += sc * vv.x; o[i].y += sc * vv.y;
                o[i].z += sc * vv.z; o[i].w += sc * vv.w;
            }
        }
    }

    // Write O tile: oh[(b*S + row)*DM + h*64 + col]
    #pragma unroll
    for (int i = 0; i < 4; i++) {
        const int row = q0 + ty * 4 + i;
        *reinterpret_cast<float4*>(&oh[(size_t)(b * SS + row) * DM + head_off + tx * 4]) = o[i];
    }
}

// ---------------------------------------------------------------------------
extern "C" void kernel_launch(void* const* d_in, const int* in_sizes, int n_in,
                              void* d_out, int out_size)
{
    const float* q     = (const float*)d_in[0];
    const float* k     = (const float*)d_in[1];
    const float* v     = (const float*)d_in[2];
    const int*   mask  = (const int*)  d_in[3];
    const float* Wq    = (const float*)d_in[4];
    const float* Wk    = (const float*)d_in[5];
    const float* Wv    = (const float*)d_in[6];
    const float* Wfc   = (const float*)d_in[7];
    const float* gamma = (const float*)d_in[8];
    const float* beta  = (const float*)d_in[9];
    float* out = (float*)d_out;
    float* attn = ((long long)out_size >= (long long)OUT_ELEMS + ATTN_ELEMS)
                      ? out + OUT_ELEMS : nullptr;

    void* p;
    cudaGetSymbolAddress(&p, g_qn); float* qn = (float*)p;
    cudaGetSymbolAddress(&p, g_qh); float* qh = (float*)p;
    cudaGetSymbolAddress(&p, g_kh); float* kh = (float*)p;
    cudaGetSymbolAddress(&p, g_vh); float* vh = (float*)p;
    cudaGetSymbolAddress(&p, g_oh); float* oh = (float*)p;

    // 1) LayerNorm(q)
    ln_kernel<<<NROWS, 256>>>(q, gamma, beta, qn);

    // 2) Projections (1/TEMP folded into Q projection)
    dim3 gg(DM / 128, NROWS / 128);
    gemm_kernel<<<gg, 256>>>(qn, Wq, qh, NROWS, DM, DM, INV_TEMP, nullptr);
    gemm_kernel<<<gg, 256>>>(k,  Wk, kh, NROWS, DM, DM, 1.0f, nullptr);
    gemm_kernel<<<gg, 256>>>(v,  Wv, vh, NROWS, DM, DM, 1.0f, nullptr);

    // 3) Fused attention (S -> mask -> attn out -> O)
    cudaFuncSetAttribute(attn_kernel, cudaFuncAttributeMaxDynamicSharedMemorySize,
                         ATTN_SMEM);
    attn_kernel<<<dim3(SS / 64, BB * NH), 256, ATTN_SMEM>>>(qh, kh, vh, mask, attn, oh);

    // 4) fc + residual
    gemm_kernel<<<gg, 256>>>(oh, Wfc, out, NROWS, DM, DM, 1.0f, q);
}

// round 6
// speedup vs baseline: 3.2942x; 3.2942x over previous
#include <cuda_runtime.h>
#include <cuda_bf16.h>
#include <cstdint>

#define BB 2
#define SS 2048
#define DM 1024
#define NH 16
#define DK 64
#define NROWS (BB * SS)
#define OUT_ELEMS (NROWS * DM)
#define ATTN_ELEMS (2LL * 16 * 2048 * 2048)
#define INV_TEMP 0.35355339059327373f

typedef __nv_bfloat16 bf16;
typedef __nv_bfloat162 bf162;

// ------------------------- device scratch (no allocs) -----------------------
__device__ __align__(128) bf16  g_qn_hi[NROWS * DM], g_qn_lo[NROWS * DM];
__device__ __align__(128) bf16  g_ki_hi[NROWS * DM], g_ki_lo[NROWS * DM];
__device__ __align__(128) bf16  g_vi_hi[NROWS * DM], g_vi_lo[NROWS * DM];
__device__ __align__(128) bf16  g_wq_hi[DM * DM], g_wq_lo[DM * DM];
__device__ __align__(128) bf16  g_wk_hi[DM * DM], g_wk_lo[DM * DM];
__device__ __align__(128) bf16  g_wv_hi[DM * DM], g_wv_lo[DM * DM];
__device__ __align__(128) bf16  g_wf_hi[DM * DM], g_wf_lo[DM * DM];
__device__ __align__(128) float g_qh[NROWS * DM];
__device__ __align__(128) bf16  g_qh_hi[NROWS * DM], g_qh_lo[NROWS * DM];
__device__ __align__(128) float g_kh[NROWS * DM];
__device__ __align__(128) bf16  g_kh_hi[NROWS * DM], g_kh_lo[NROWS * DM];
__device__ __align__(128) float g_vh[NROWS * DM];
__device__ __align__(128) bf16  g_oh_hi[NROWS * DM], g_oh_lo[NROWS * DM];
__device__ __align__(128) float g_P[BB * NH * DK * DK];
__device__ int g_flag;

// ------------------------- helpers ------------------------------------------
__device__ __forceinline__ uint32_t smem_u32(const void* p) {
    uint32_t a;
    asm("{ .reg .u64 t; cvta.to.shared.u64 t, %1; cvt.u32.u64 %0, t; }"
        : "=r"(a) : "l"(p));
    return a;
}
__device__ __forceinline__ void cp16(uint32_t saddr, const void* g) {
    asm volatile("cp.async.cg.shared.global [%0], [%1], 16;"
                 :: "r"(saddr), "l"(g) : "memory");
}
__device__ __forceinline__ void cp_commit() {
    asm volatile("cp.async.commit_group;" ::: "memory");
}
__device__ __forceinline__ void cp_wait0() {
    asm volatile("cp.async.wait_group 0;" ::: "memory");
}
__device__ __forceinline__ void cp_wait1() {
    asm volatile("cp.async.wait_group 1;" ::: "memory");
}
__device__ __forceinline__ void ldsm4(uint32_t* r, uint32_t addr) {
    asm volatile("ldmatrix.sync.aligned.m8n8.x4.shared.b16 {%0,%1,%2,%3}, [%4];"
                 : "=r"(r[0]), "=r"(r[1]), "=r"(r[2]), "=r"(r[3]) : "r"(addr));
}
__device__ __forceinline__ void mma16816(float* d, const uint32_t* a,
                                         const uint32_t* b) {
    asm volatile(
        "mma.sync.aligned.m16n8k16.row.col.f32.bf16.bf16.f32 "
        "{%0,%1,%2,%3}, {%4,%5,%6,%7}, {%8,%9}, {%0,%1,%2,%3};"
        : "+f"(d[0]), "+f"(d[1]), "+f"(d[2]), "+f"(d[3])
        : "r"(a[0]), "r"(a[1]), "r"(a[2]), "r"(a[3]), "r"(b[0]), "r"(b[1]));
}
__device__ __forceinline__ void split_pair(float x, float y, bf162* hi, bf162* lo) {
    bf162 h = __floats2bfloat162_rn(x, y);
    *hi = h;
    *lo = __floats2bfloat162_rn(x - __bfloat162float(h.x), y - __bfloat162float(h.y));
}

// ------------------------- small prep kernels --------------------------------
__global__ void initk() {
    int i = blockIdx.x * 256 + threadIdx.x;
    if (i < BB * NH * DK * DK) g_P[i] = 0.0f;
    if (i == 0) g_flag = 1;
}

__global__ void maskchk(const int* __restrict__ mask) {
    const int4* m4 = reinterpret_cast<const int4*>(mask);
    const size_t total = (size_t)BB * SS * SS / 4;
    size_t i = (size_t)blockIdx.x * 256 + threadIdx.x;
    size_t stride = (size_t)gridDim.x * 256;
    int bad = 0;
    for (size_t j = i; j < total; j += stride) {
        int4 m = m4[j];
        if (!(m.x && m.y && m.z && m.w)) bad = 1;
    }
    if (bad) g_flag = 0;
}

__global__ void ln_kernel(const float* __restrict__ q,
                          const float* __restrict__ gamma,
                          const float* __restrict__ beta,
                          bf16* __restrict__ out_hi, bf16* __restrict__ out_lo) {
    __shared__ float red[16];
    const int row = blockIdx.x;
    const int tid = threadIdx.x;
    const float4 v = reinterpret_cast<const float4*>(q)[row * 256 + tid];
    float s  = v.x + v.y + v.z + v.w;
    float s2 = v.x * v.x + v.y * v.y + v.z * v.z + v.w * v.w;
    #pragma unroll
    for (int o = 16; o > 0; o >>= 1) {
        s  += __shfl_xor_sync(0xffffffffu, s,  o);
        s2 += __shfl_xor_sync(0xffffffffu, s2, o);
    }
    if ((tid & 31) == 0) { red[tid >> 5] = s; red[8 + (tid >> 5)] = s2; }
    __syncthreads();
    if (tid < 32) {
        s  = (tid < 8) ? red[tid]     : 0.0f;
        s2 = (tid < 8) ? red[8 + tid] : 0.0f;
        #pragma unroll
        for (int o = 4; o > 0; o >>= 1) {
            s  += __shfl_xor_sync(0xffffffffu, s,  o);
            s2 += __shfl_xor_sync(0xffffffffu, s2, o);
        }
        if (tid == 0) { red[0] = s; red[8] = s2; }
    }
    __syncthreads();
    const float mu   = red[0] * (1.0f / 1024.0f);
    const float var  = red[8] * (1.0f / 1024.0f) - mu * mu;
    const float rstd = rsqrtf(var + 1e-6f);
    const float4 g  = reinterpret_cast<const float4*>(gamma)[tid];
    const float4 bb = reinterpret_cast<const float4*>(beta)[tid];
    float y0 = ((v.x - mu) * rstd * g.x + bb.x) * INV_TEMP;
    float y1 = ((v.y - mu) * rstd * g.y + bb.y) * INV_TEMP;
    float y2 = ((v.z - mu) * rstd * g.z + bb.z) * INV_TEMP;
    float y3 = ((v.w - mu) * rstd * g.w + bb.w) * INV_TEMP;
    bf162 h0, l0, h1, l1;
    split_pair(y0, y1, &h0, &l0);
    split_pair(y2, y3, &h1, &l1);
    bf162* oh = reinterpret_cast<bf162*>(out_hi);
    bf162* ol = reinterpret_cast<bf162*>(out_lo);
    const int b2 = (row * 256 + tid) * 2;
    oh[b2] = h0; oh[b2 + 1] = h1;
    ol[b2] = l0; ol[b2 + 1] = l1;
}

__global__ void splitk(const float* __restrict__ x, bf16* __restrict__ hi,
                       bf16* __restrict__ lo, int n4) {
    int i = blockIdx.x * 256 + threadIdx.x;
    if (i >= n4) return;
    float4 v = reinterpret_cast<const float4*>(x)[i];
    bf162 h0, l0, h1, l1;
    split_pair(v.x, v.y, &h0, &l0);
    split_pair(v.z, v.w, &h1, &l1);
    reinterpret_cast<bf162*>(hi)[i * 2]     = h0;
    reinterpret_cast<bf162*>(hi)[i * 2 + 1] = h1;
    reinterpret_cast<bf162*>(lo)[i * 2]     = l0;
    reinterpret_cast<bf162*>(lo)[i * 2 + 1] = l1;
}

// W[K][N] -> WT[n][k] hi/lo bf16
__global__ void wprep(const float* __restrict__ W, bf16* __restrict__ Thi,
                      bf16* __restrict__ Tlo) {
    __shared__ float t[32][33];
    const int n0 = blockIdx.x * 32, k0 = blockIdx.y * 32;
    const int tx = threadIdx.x, ty = threadIdx.y;
    #pragma unroll
    for (int r = 0; r < 4; r++)
        t[ty + r * 8][tx] = W[(size_t)(k0 + ty + r * 8) * DM + n0 + tx];
    __syncthreads();
    #pragma unroll
    for (int r = 0; r < 4; r++) {
        const int nl = ty + r * 8;
        const float x = t[tx][nl];
        bf16 h = __float2bfloat16(x);
        Thi[(size_t)(n0 + nl) * DM + k0 + tx] = h;
        Tlo[(size_t)(n0 + nl) * DM + k0 + tx] = __float2bfloat16(x - __bfloat162float(h));
    }
}

// ------------------------- mma.sync GEMM -------------------------------------
// C[M,N] = A[M,K] @ BT[N,K]^T, split bf16 (3-term), fp32 accum.
// 128x128 CTA tile, BK=32, 2-stage cp.async, 8 warps (2M x 4N, 64x32 each).
#define ROWB 80                      // 40 bf16 per row (32 used + 8 pad)
#define BUFB (128 * ROWB)            // 10240 B
#define STAGEB (4 * BUFB)            // Ah, Al, Bh, Bl
#define TG_SMEM (2 * STAGEB)         // 81920 B

__global__ __launch_bounds__(256, 1)
void tgemm(const bf16* __restrict__ Ahi, const bf16* __restrict__ Alo,
           const bf16* __restrict__ Bhi, const bf16* __restrict__ Blo,
           float* __restrict__ Cf, bf16* __restrict__ Chi, bf16* __restrict__ Clo,
           const float* __restrict__ resid, int N, int K)
{
    extern __shared__ __align__(128) char sb[];
    const uint32_t smb = smem_u32(sb);
    const int tid = threadIdx.x, lane = tid & 31, wid = tid >> 5;
    const int bm = blockIdx.y * 128, bn = blockIdx.x * 128;
    const int wm = (wid >> 2) * 64, wn = (wid & 3) * 32;

    // per-thread cp.async mapping: 8 chunks of 16B (buf = i>>1)
    int ldRow[8]; uint32_t ldSm[8]; const bf16* ldG[8];
    #pragma unroll
    for (int i = 0; i < 8; i++) {
        const int buf = i >> 1;
        const int chunk = tid + (i & 1) * 256;       // 0..511
        const int r = chunk >> 2, j = chunk & 3;     // j: 16B unit (8 bf16)
        ldRow[i] = r;
        ldSm[i] = smb + buf * BUFB + r * ROWB + j * 16;
        const bf16* base = (buf == 0) ? Ahi : (buf == 1) ? Alo
                         : (buf == 2) ? Bhi : Blo;
        const int rowg = (buf < 2) ? (bm + r) : (bn + r);
        ldG[i] = base + (size_t)rowg * K + j * 8;
    }

    // ldmatrix lane offsets
    const uint32_t aOff = (uint32_t)((wm + (lane & 15)) * ROWB + (((lane >> 4) << 3)) * 2);
    const uint32_t bOff = (uint32_t)((wn + ((lane >> 4) << 3) + (lane & 7)) * ROWB
                                     + ((((lane >> 3) & 1) << 3)) * 2);

    float acc[4][4][4] = {};
    const int NT = K / 32;

    // preload stage 0
    #pragma unroll
    for (int i = 0; i < 8; i++) cp16(ldSm[i], ldG[i]);
    cp_commit();

    for (int t = 0; t < NT; t++) {
        if (t + 1 < NT) {
            const uint32_t so = ((t + 1) & 1) * STAGEB;
            const int kc = (t + 1) * 32;
            #pragma unroll
            for (int i = 0; i < 8; i++) cp16(ldSm[i] + so, ldG[i] + kc);
            cp_commit();
            cp_wait1();
        } else {
            cp_wait0();
        }
        __syncthreads();

        const uint32_t st = smb + (t & 1) * STAGEB;
        #pragma unroll
        for (int ks = 0; ks < 32; ks += 16) {
            uint32_t ah[4][4], al[4][4], bh[2][4], bl[2][4];
            #pragma unroll
            for (int mi = 0; mi < 4; mi++) {
                ldsm4(ah[mi], st + aOff + mi * (16 * ROWB) + ks * 2);
                ldsm4(al[mi], st + BUFB + aOff + mi * (16 * ROWB) + ks * 2);
            }
            #pragma unroll
            for (int n2 = 0; n2 < 2; n2++) {
                ldsm4(bh[n2], st + 2 * BUFB + bOff + n2 * (16 * ROWB) + ks * 2);
                ldsm4(bl[n2], st + 3 * BUFB + bOff + n2 * (16 * ROWB) + ks * 2);
            }
            #pragma unroll
            for (int mi = 0; mi < 4; mi++)
                #pragma unroll
                for (int ni = 0; ni < 4; ni++) {
                    const uint32_t* bph = &bh[ni >> 1][(ni & 1) * 2];
                    const uint32_t* bpl = &bl[ni >> 1][(ni & 1) * 2];
                    mma16816(acc[mi][ni], ah[mi], bph);
                    mma16816(acc[mi][ni], ah[mi], bpl);
                    mma16816(acc[mi][ni], al[mi], bph);
                }
        }
        __syncthreads();
    }

    // epilogue
    #pragma unroll
    for (int mi = 0; mi < 4; mi++)
        #pragma unroll
        for (int ni = 0; ni < 4; ni++) {
            #pragma unroll
            for (int half = 0; half < 2; half++) {
                const int r = bm + wm + mi * 16 + (lane >> 2) + half * 8;
                const int c = bn + wn + ni * 8 + (lane & 3) * 2;
                const size_t idx = (size_t)r * N + c;
                float d0 = acc[mi][ni][half * 2 + 0];
                float d1 = acc[mi][ni][half * 2 + 1];
                if (resid) {
                    const float2 q2 = *reinterpret_cast<const float2*>(&resid[idx]);
                    d0 += q2.x; d1 += q2.y;
                }
                if (Cf) *reinterpret_cast<float2*>(&Cf[idx]) = make_float2(d0, d1);
                if (Chi) {
                    bf162 h, l;
                    split_pair(d0, d1, &h, &l);
                    *reinterpret_cast<bf162*>(&Chi[idx]) = h;
                    *reinterpret_cast<bf162*>(&Clo[idx]) = l;
                }
            }
        }
}

// ------------------------- S = Q K^T (masked) --------------------------------
// per block: 128 q-rows x 128 k-cols, K=64. Single-stage cp.async load.
#define ROWS_S 144                   // 72 bf16/row (64 used + 8 pad)
#define BUFS (128 * ROWS_S)          // 18432
#define SA_SMEM (4 * BUFS)           // 73728

__global__ __launch_bounds__(256, 1)
void sgemm_attn(const bf16* __restrict__ Ahi, const bf16* __restrict__ Alo,
                const bf16* __restrict__ Bhi, const bf16* __restrict__ Blo,
                const int* __restrict__ mask, float* __restrict__ attn)
{
    extern __shared__ __align__(128) char sb[];
    const uint32_t smb = smem_u32(sb);
    const int tid = threadIdx.x, lane = tid & 31, wid = tid >> 5;
    const int k0t = blockIdx.x * 128;
    const int q0 = blockIdx.y * 128;
    const int bh = blockIdx.z;
    const int b = bh >> 4, h = bh & 15;
    const size_t hoff = (size_t)h * DK;
    const int wm = (wid >> 2) * 64, wn = (wid & 3) * 32;

    // load: 4 buffers x 1024 chunks (128 rows x 8 x16B) = 16/thread
    #pragma unroll
    for (int i = 0; i < 16; i++) {
        const int buf = i >> 2;
        const int chunk = tid + (i & 3) * 256;     // 0..1023
        const int r = chunk >> 3, j = chunk & 7;
        const bf16* base = (buf == 0) ? Ahi : (buf == 1) ? Alo
                         : (buf == 2) ? Bhi : Blo;
        const int rowg = (buf < 2) ? (b * SS + q0 + r) : (b * SS + k0t + r);
        cp16(smb + buf * BUFS + r * ROWS_S + j * 16,
             base + (size_t)rowg * DM + hoff + j * 8);
    }
    cp_commit();

    const uint32_t aOff = (uint32_t)((wm + (lane & 15)) * ROWS_S + (((lane >> 4) << 3)) * 2);
    const uint32_t bOff = (uint32_t)((wn + ((lane >> 4) << 3) + (lane & 7)) * ROWS_S
                                     + ((((lane >> 3) & 1) << 3)) * 2);

    cp_wait0();
    __syncthreads();

    float acc[4][4][4] = {};
    #pragma unroll
    for (int ks = 0; ks < 64; ks += 16) {
        uint32_t ah[4][4], al[4][4], bh2[2][4], bl2[2][4];
        #pragma unroll
        for (int mi = 0; mi < 4; mi++) {
            ldsm4(ah[mi], smb + aOff + mi * (16 * ROWS_S) + ks * 2);
            ldsm4(al[mi], smb + BUFS + aOff + mi * (16 * ROWS_S) + ks * 2);
        }
        #pragma unroll
        for (int n2 = 0; n2 < 2; n2++) {
            ldsm4(bh2[n2], smb + 2 * BUFS + bOff + n2 * (16 * ROWS_S) + ks * 2);
            ldsm4(bl2[n2], smb + 3 * BUFS + bOff + n2 * (16 * ROWS_S) + ks * 2);
        }
        #pragma unroll
        for (int mi = 0; mi < 4; mi++)
            #pragma unroll
            for (int ni = 0; ni < 4; ni++) {
                const uint32_t* bph = &bh2[ni >> 1][(ni & 1) * 2];
                const uint32_t* bpl = &bl2[ni >> 1][(ni & 1) * 2];
                mma16816(acc[mi][ni], ah[mi], bph);
                mma16816(acc[mi][ni], ah[mi], bpl);
                mma16816(acc[mi][ni], al[mi], bph);
            }
    }

    const int allones = g_flag;
    #pragma unroll
    for (int mi = 0; mi < 4; mi++)
        #pragma unroll
        for (int ni = 0; ni < 4; ni++) {
            #pragma unroll
            for (int half = 0; half < 2; half++) {
                const int r = q0 + wm + mi * 16 + (lane >> 2) + half * 8;
                const int c = k0t + wn + ni * 8 + (lane & 3) * 2;
                float d0 = acc[mi][ni][half * 2 + 0];
                float d1 = acc[mi][ni][half * 2 + 1];
                if (!allones) {
                    const int2 m = *reinterpret_cast<const int2*>(
                        &mask[((size_t)b * SS + r) * SS + c]);
                    if (m.x == 0) d0 = -1e9f;
                    if (m.y == 0) d1 = -1e9f;
                }
                *reinterpret_cast<float2*>(
                    &attn[((size_t)bh * SS + r) * SS + c]) = make_float2(d0, d1);
            }
        }
}

// ------------------------- P = K^T V (64x64 per bh), split-K -----------------
__global__ __launch_bounds__(256)
void pk_kernel(const float* __restrict__ kh, const float* __restrict__ vh)
{
    if (g_flag == 0) return;
    __shared__ float Ks[32][68];
    __shared__ float Vs[32][68];
    const int bh = blockIdx.x, split = blockIdx.y;
    const int b = bh >> 4, h = bh & 15;
    const size_t hoff = (size_t)h * DK;
    const int tid = threadIdx.x;
    const int tx = tid & 15, ty = tid >> 4;
    float acc[4][4] = {};
    for (int it = 0; it < 8; it++) {
        const int s0 = split * 256 + it * 32;
        __syncthreads();
        #pragma unroll
        for (int t = 0; t < 2; t++) {
            const int idx = tid + t * 256;
            const int rr = idx >> 4, c4 = idx & 15;
            const size_t g = ((size_t)(b * SS + s0 + rr) * DM + hoff) / 4 + c4;
            *reinterpret_cast<float4*>(&Ks[rr][c4 * 4]) =
                reinterpret_cast<const float4*>(kh)[g];
            *reinterpret_cast<float4*>(&Vs[rr][c4 * 4]) =
                reinterpret_cast<const float4*>(vh)[g];
        }
        __syncthreads();
        #pragma unroll 4
        for (int s = 0; s < 32; s++) {
            const float4 vv = *reinterpret_cast<const float4*>(&Vs[s][tx * 4]);
            #pragma unroll
            for (int i = 0; i < 4; i++) {
                const float kv = Ks[s][ty * 4 + i];
                acc[i][0] += kv * vv.x; acc[i][1] += kv * vv.y;
                acc[i][2] += kv * vv.z; acc[i][3] += kv * vv.w;
            }
        }
    }
    #pragma unroll
    for (int i = 0; i < 4; i++)
        #pragma unroll
        for (int j = 0; j < 4; j++)
            atomicAdd(&g_P[bh * (DK * DK) + (ty * 4 + i) * DK + tx * 4 + j], acc[i][j]);
}

// ------------------------- O = Qs @ P (fast path) ----------------------------
__global__ __launch_bounds__(256)
void ofast_kernel(const float* __restrict__ qh)
{
    if (g_flag == 0) return;
    __shared__ float Qs[64][68];
    __shared__ float Ps[64][64];
    const int q0 = blockIdx.x * 64;
    const int bh = blockIdx.y;
    const int b = bh >> 4, h = bh & 15;
    const size_t hoff = (size_t)h * DK;
    const int tid = threadIdx.x;
    const int tx = tid & 15, ty = tid >> 4;
    #pragma unroll
    for (int t = 0; t < 4; t++) {
        const int idx = tid + t * 256;
        const int rr = idx >> 4, c4 = idx & 15;
        *reinterpret_cast<float4*>(&Qs[rr][c4 * 4]) =
            reinterpret_cast<const float4*>(qh)[((size_t)(b * SS + q0 + rr) * DM + hoff) / 4 + c4];
        *reinterpret_cast<float4*>(&Ps[rr][c4 * 4]) =
            reinterpret_cast<const float4*>(g_P)[(size_t)bh * (DK * DK) / 4 + rr * 16 + c4];
    }
    __syncthreads();
    float acc[4][4] = {};
    #pragma unroll 8
    for (int d = 0; d < 64; d++) {
        const float4 pv = *reinterpret_cast<const float4*>(&Ps[d][tx * 4]);
        #pragma unroll
        for (int i = 0; i < 4; i++) {
            const float qv = Qs[ty * 4 + i][d];
            acc[i][0] += qv * pv.x; acc[i][1] += qv * pv.y;
            acc[i][2] += qv * pv.z; acc[i][3] += qv * pv.w;
        }
    }
    #pragma unroll
    for (int i = 0; i < 4; i++) {
        const size_t base = (size_t)(b * SS + q0 + ty * 4 + i) * DM + hoff + tx * 4;
        bf162 h0, l0, h1, l1;
        split_pair(acc[i][0], acc[i][1], &h0, &l0);
        split_pair(acc[i][2], acc[i][3], &h1, &l1);
        bf162* ph = reinterpret_cast<bf162*>(&g_oh_hi[base]);
        bf162* pl = reinterpret_cast<bf162*>(&g_oh_lo[base]);
        ph[0] = h0; ph[1] = h1;
        pl[0] = l0; pl[1] = l1;
    }
}

// ------------------------- O = attn @ V (fallback) ---------------------------
__global__ __launch_bounds__(256)
void ofb_kernel(const float* __restrict__ attn, const float* __restrict__ vh)
{
    if (g_flag != 0) return;
    __shared__ float As[64][68];
    __shared__ float Vs[64][68];
    const int q0 = blockIdx.x * 64;
    const int bh = blockIdx.y;
    const int b = bh >> 4, h = bh & 15;
    const size_t hoff = (size_t)h * DK;
    const int tid = threadIdx.x;
    const int tx = tid & 15, ty = tid >> 4;
    float acc[4][4] = {};
    for (int k0 = 0; k0 < SS; k0 += 64) {
        __syncthreads();
        #pragma unroll
        for (int t = 0; t < 4; t++) {
            const int idx = tid + t * 256;
            const int rr = idx >> 4, c4 = idx & 15;
            *reinterpret_cast<float4*>(&As[rr][c4 * 4]) =
                reinterpret_cast<const float4*>(attn)[(((size_t)bh * SS + q0 + rr) * SS + k0) / 4 + c4];
            *reinterpret_cast<float4*>(&Vs[rr][c4 * 4]) =
                reinterpret_cast<const float4*>(vh)[((size_t)(b * SS + k0 + rr) * DM + hoff) / 4 + c4];
        }
        __syncthreads();
        #pragma unroll 8
        for (int kk = 0; kk < 64; kk++) {
            const float4 vv = *reinterpret_cast<const float4*>(&Vs[kk][tx * 4]);
            #pragma unroll
            for (int i = 0; i < 4; i++) {
                const float sv = As[ty * 4 + i][kk];
                acc[i][0] += sv * vv.x; acc[i][1] += sv * vv.y;
                acc[i][2] += sv * vv.z; acc[i][3] += sv * vv.w;
            }
        }
    }
    #pragma unroll
    for (int i = 0; i < 4; i++) {
        const size_t base = (size_t)(b * SS + q0 + ty * 4 + i) * DM + hoff + tx * 4;
        bf162 h0, l0, h1, l1;
        split_pair(acc[i][0], acc[i][1], &h0, &l0);
        split_pair(acc[i][2], acc[i][3], &h1, &l1);
        bf162* ph = reinterpret_cast<bf162*>(&g_oh_hi[base]);
        bf162* pl = reinterpret_cast<bf162*>(&g_oh_lo[base]);
        ph[0] = h0; ph[1] = h1;
        pl[0] = l0; pl[1] = l1;
    }
}

// ---------------------------------------------------------------------------
extern "C" void kernel_launch(void* const* d_in, const int* in_sizes, int n_in,
                              void* d_out, int out_size)
{
    const float* q     = (const float*)d_in[0];
    const float* k     = (const float*)d_in[1];
    const float* v     = (const float*)d_in[2];
    const int*   mask  = (const int*)  d_in[3];
    const float* Wq    = (const float*)d_in[4];
    const float* Wk    = (const float*)d_in[5];
    const float* Wv    = (const float*)d_in[6];
    const float* Wfc   = (const float*)d_in[7];
    const float* gamma = (const float*)d_in[8];
    const float* beta  = (const float*)d_in[9];
    float* out = (float*)d_out;
    float* attn = ((long long)out_size >= (long long)OUT_ELEMS + ATTN_ELEMS)
                      ? out + OUT_ELEMS : nullptr;

    void* p;
    #define SYM(T, name, sym) cudaGetSymbolAddress(&p, sym); T* name = (T*)p
    SYM(bf16, qn_hi, g_qn_hi); SYM(bf16, qn_lo, g_qn_lo);
    SYM(bf16, ki_hi, g_ki_hi); SYM(bf16, ki_lo, g_ki_lo);
    SYM(bf16, vi_hi, g_vi_hi); SYM(bf16, vi_lo, g_vi_lo);
    SYM(bf16, wq_hi, g_wq_hi); SYM(bf16, wq_lo, g_wq_lo);
    SYM(bf16, wk_hi, g_wk_hi); SYM(bf16, wk_lo, g_wk_lo);
    SYM(bf16, wv_hi, g_wv_hi); SYM(bf16, wv_lo, g_wv_lo);
    SYM(bf16, wf_hi, g_wf_hi); SYM(bf16, wf_lo, g_wf_lo);
    SYM(float, qh, g_qh); SYM(bf16, qh_hi, g_qh_hi); SYM(bf16, qh_lo, g_qh_lo);
    SYM(float, kh, g_kh); SYM(bf16, kh_hi, g_kh_hi); SYM(bf16, kh_lo, g_kh_lo);
    SYM(float, vh, g_vh);
    SYM(bf16, oh_hi, g_oh_hi); SYM(bf16, oh_lo, g_oh_lo);
    #undef SYM

    cudaFuncSetAttribute(tgemm, cudaFuncAttributeMaxDynamicSharedMemorySize, TG_SMEM);
    cudaFuncSetAttribute(sgemm_attn, cudaFuncAttributeMaxDynamicSharedMemorySize, SA_SMEM);

    // prep
    initk<<<512, 256>>>();
    maskchk<<<2048, 256>>>(mask);
    ln_kernel<<<NROWS, 256>>>(q, gamma, beta, qn_hi, qn_lo);
    splitk<<<NROWS * DM / 4 / 256, 256>>>(k, ki_hi, ki_lo, NROWS * DM / 4);
    splitk<<<NROWS * DM / 4 / 256, 256>>>(v, vi_hi, vi_lo, NROWS * DM / 4);
    dim3 wg(32, 32), wb(32, 8);
    wprep<<<wg, wb>>>(Wq, wq_hi, wq_lo);
    wprep<<<wg, wb>>>(Wk, wk_hi, wk_lo);
    wprep<<<wg, wb>>>(Wv, wv_hi, wv_lo);
    wprep<<<wg, wb>>>(Wfc, wf_hi, wf_lo);

    // projections (tensor cores via mma.sync)
    dim3 gg(DM / 128, NROWS / 128);
    tgemm<<<gg, 256, TG_SMEM>>>(qn_hi, qn_lo, wq_hi, wq_lo,
                                qh, qh_hi, qh_lo, nullptr, DM, DM);
    tgemm<<<gg, 256, TG_SMEM>>>(ki_hi, ki_lo, wk_hi, wk_lo,
                                kh, kh_hi, kh_lo, nullptr, DM, DM);
    tgemm<<<gg, 256, TG_SMEM>>>(vi_hi, vi_lo, wv_hi, wv_lo,
                                vh, nullptr, nullptr, nullptr, DM, DM);

    // attn scores + mask
    if (attn)
        sgemm_attn<<<dim3(SS / 128, SS / 128, BB * NH), 256, SA_SMEM>>>(
            qh_hi, qh_lo, kh_hi, kh_lo, mask, attn);

    // O: fast path (mask all-ones) or fallback
    pk_kernel<<<dim3(BB * NH, 8), 256>>>(kh, vh);
    ofast_kernel<<<dim3(SS / 64, BB * NH), 256>>>(qh);
    if (attn)
        ofb_kernel<<<dim3(SS / 64, BB * NH), 256>>>(attn, vh);

    // fc + residual
    tgemm<<<gg, 256, TG_SMEM>>>(oh_hi, oh_lo, wf_hi, wf_lo,
                                out, nullptr, nullptr, q, DM, DM);
}

// round 7
// speedup vs baseline: 3.7980x; 1.1529x over previous
#include <cuda_runtime.h>
#include <cuda_fp16.h>
#include <cstdint>

#define BB 2
#define SS 2048
#define DM 1024
#define NH 16
#define DK 64
#define NROWS (BB * SS)
#define OUT_ELEMS (NROWS * DM)
#define ATTN_ELEMS (2LL * 16 * 2048 * 2048)
#define INV_TEMP 0.35355339059327373f

typedef __half fp16;

// ------------------------- device scratch (no allocs) -----------------------
__device__ __align__(128) fp16  g_qn_hi[NROWS * DM], g_qn_lo[NROWS * DM];
__device__ __align__(128) fp16  g_ki_hi[NROWS * DM], g_ki_lo[NROWS * DM];
__device__ __align__(128) fp16  g_vi_hi[NROWS * DM], g_vi_lo[NROWS * DM];
__device__ __align__(128) fp16  g_wq_hi[DM * DM];
__device__ __align__(128) fp16  g_wk_hi[DM * DM];
__device__ __align__(128) fp16  g_wv_hi[DM * DM];
__device__ __align__(128) fp16  g_wf_hi[DM * DM];
__device__ __align__(128) float g_qh[NROWS * DM];
__device__ __align__(128) fp16  g_qh_hi[NROWS * DM], g_qh_lo[NROWS * DM];
__device__ __align__(128) float g_kh[NROWS * DM];
__device__ __align__(128) fp16  g_kh_hi[NROWS * DM];
__device__ __align__(128) float g_vh[NROWS * DM];
__device__ __align__(128) fp16  g_oh_hi[NROWS * DM], g_oh_lo[NROWS * DM];
__device__ __align__(128) float g_P[BB * NH * DK * DK];
__device__ int g_flag;

// ------------------------- helpers ------------------------------------------
__device__ __forceinline__ uint32_t smem_u32(const void* p) {
    uint32_t a;
    asm("{ .reg .u64 t; cvta.to.shared.u64 t, %1; cvt.u32.u64 %0, t; }"
        : "=r"(a) : "l"(p));
    return a;
}
__device__ __forceinline__ void cp16(uint32_t saddr, const void* g) {
    asm volatile("cp.async.cg.shared.global [%0], [%1], 16;"
                 :: "r"(saddr), "l"(g) : "memory");
}
__device__ __forceinline__ void cp_commit() {
    asm volatile("cp.async.commit_group;" ::: "memory");
}
__device__ __forceinline__ void cp_wait0() {
    asm volatile("cp.async.wait_group 0;" ::: "memory");
}
__device__ __forceinline__ void cp_wait1() {
    asm volatile("cp.async.wait_group 1;" ::: "memory");
}
__device__ __forceinline__ void ldsm4(uint32_t* r, uint32_t addr) {
    asm volatile("ldmatrix.sync.aligned.m8n8.x4.shared.b16 {%0,%1,%2,%3}, [%4];"
                 : "=r"(r[0]), "=r"(r[1]), "=r"(r[2]), "=r"(r[3]) : "r"(addr));
}
__device__ __forceinline__ void mma16816(float* d, const uint32_t* a,
                                         const uint32_t* b) {
    asm volatile(
        "mma.sync.aligned.m16n8k16.row.col.f32.f16.f16.f32 "
        "{%0,%1,%2,%3}, {%4,%5,%6,%7}, {%8,%9}, {%0,%1,%2,%3};"
        : "+f"(d[0]), "+f"(d[1]), "+f"(d[2]), "+f"(d[3])
        : "r"(a[0]), "r"(a[1]), "r"(a[2]), "r"(a[3]), "r"(b[0]), "r"(b[1]));
}
__device__ __forceinline__ void split_pair(float x, float y, __half2* hi,
                                           __half2* lo) {
    __half2 h = __floats2half2_rn(x, y);
    *hi = h;
    *lo = __floats2half2_rn(x - __half2float(__low2half(h)),
                            y - __half2float(__high2half(h)));
}

// ------------------------- small prep kernels --------------------------------
__global__ void initk() {
    int i = blockIdx.x * 256 + threadIdx.x;
    if (i < BB * NH * DK * DK) g_P[i] = 0.0f;
    if (i == 0) g_flag = 1;
}

__global__ void maskchk(const int* __restrict__ mask) {
    const int4* m4 = reinterpret_cast<const int4*>(mask);
    const size_t total = (size_t)BB * SS * SS / 4;
    size_t i = (size_t)blockIdx.x * 256 + threadIdx.x;
    size_t stride = (size_t)gridDim.x * 256;
    int bad = 0;
    for (size_t j = i; j < total; j += stride) {
        int4 m = __ldcs(&m4[j]);
        if (!(m.x && m.y && m.z && m.w)) bad = 1;
    }
    if (bad) g_flag = 0;
}

__global__ void ln_kernel(const float* __restrict__ q,
                          const float* __restrict__ gamma,
                          const float* __restrict__ beta,
                          fp16* __restrict__ out_hi, fp16* __restrict__ out_lo) {
    __shared__ float red[16];
    const int row = blockIdx.x;
    const int tid = threadIdx.x;
    const float4 v = reinterpret_cast<const float4*>(q)[row * 256 + tid];
    float s  = v.x + v.y + v.z + v.w;
    float s2 = v.x * v.x + v.y * v.y + v.z * v.z + v.w * v.w;
    #pragma unroll
    for (int o = 16; o > 0; o >>= 1) {
        s  += __shfl_xor_sync(0xffffffffu, s,  o);
        s2 += __shfl_xor_sync(0xffffffffu, s2, o);
    }
    if ((tid & 31) == 0) { red[tid >> 5] = s; red[8 + (tid >> 5)] = s2; }
    __syncthreads();
    if (tid < 32) {
        s  = (tid < 8) ? red[tid]     : 0.0f;
        s2 = (tid < 8) ? red[8 + tid] : 0.0f;
        #pragma unroll
        for (int o = 4; o > 0; o >>= 1) {
            s  += __shfl_xor_sync(0xffffffffu, s,  o);
            s2 += __shfl_xor_sync(0xffffffffu, s2, o);
        }
        if (tid == 0) { red[0] = s; red[8] = s2; }
    }
    __syncthreads();
    const float mu   = red[0] * (1.0f / 1024.0f);
    const float var  = red[8] * (1.0f / 1024.0f) - mu * mu;
    const float rstd = rsqrtf(var + 1e-6f);
    const float4 g  = reinterpret_cast<const float4*>(gamma)[tid];
    const float4 bb = reinterpret_cast<const float4*>(beta)[tid];
    float y0 = ((v.x - mu) * rstd * g.x + bb.x) * INV_TEMP;
    float y1 = ((v.y - mu) * rstd * g.y + bb.y) * INV_TEMP;
    float y2 = ((v.z - mu) * rstd * g.z + bb.z) * INV_TEMP;
    float y3 = ((v.w - mu) * rstd * g.w + bb.w) * INV_TEMP;
    __half2 h0, l0, h1, l1;
    split_pair(y0, y1, &h0, &l0);
    split_pair(y2, y3, &h1, &l1);
    __half2* oh = reinterpret_cast<__half2*>(out_hi);
    __half2* ol = reinterpret_cast<__half2*>(out_lo);
    const int b2 = (row * 256 + tid) * 2;
    oh[b2] = h0; oh[b2 + 1] = h1;
    ol[b2] = l0; ol[b2 + 1] = l1;
}

__global__ void splitk(const float* __restrict__ x, fp16* __restrict__ hi,
                       fp16* __restrict__ lo, int n4) {
    int i = blockIdx.x * 256 + threadIdx.x;
    if (i >= n4) return;
    float4 v = reinterpret_cast<const float4*>(x)[i];
    __half2 h0, l0, h1, l1;
    split_pair(v.x, v.y, &h0, &l0);
    split_pair(v.z, v.w, &h1, &l1);
    reinterpret_cast<__half2*>(hi)[i * 2]     = h0;
    reinterpret_cast<__half2*>(hi)[i * 2 + 1] = h1;
    reinterpret_cast<__half2*>(lo)[i * 2]     = l0;
    reinterpret_cast<__half2*>(lo)[i * 2 + 1] = l1;
}

// W[K][N] -> WT[n][k] hi fp16 (transpose)
__global__ void wprep(const float* __restrict__ W, fp16* __restrict__ Thi) {
    __shared__ float t[32][33];
    const int n0 = blockIdx.x * 32, k0 = blockIdx.y * 32;
    const int tx = threadIdx.x, ty = threadIdx.y;
    #pragma unroll
    for (int r = 0; r < 4; r++)
        t[ty + r * 8][tx] = W[(size_t)(k0 + ty + r * 8) * DM + n0 + tx];
    __syncthreads();
    #pragma unroll
    for (int r = 0; r < 4; r++) {
        const int nl = ty + r * 8;
        Thi[(size_t)(n0 + nl) * DM + k0 + tx] = __float2half_rn(t[tx][nl]);
    }
}

// ------------------------- mma.sync GEMM (fp16 2-term) -----------------------
// C[M,N] = (Ahi+Alo)[M,K] @ Bh[N,K]^T, fp32 accum.
// 128x128 CTA tile, BK=32, 2-stage cp.async, 8 warps (2M x 4N, 64x32 each).
#define ROWB 80                      // 32 fp16 (64B) + 16B pad
#define BUFB (128 * ROWB)            // 10240 B
#define STAGEB (3 * BUFB)            // Ah, Al, Bh
#define TG_SMEM (2 * STAGEB)         // 61440 B

__global__ __launch_bounds__(256, 1)
void tgemm(const fp16* __restrict__ Ahi, const fp16* __restrict__ Alo,
           const fp16* __restrict__ Bh, float* __restrict__ Cf,
           fp16* __restrict__ Chi, fp16* __restrict__ Clo,
           const float* __restrict__ resid, int N, int K)
{
    extern __shared__ __align__(128) char sb[];
    const uint32_t smb = smem_u32(sb);
    const int tid = threadIdx.x, lane = tid & 31, wid = tid >> 5;
    const int bm = blockIdx.y * 128, bn = blockIdx.x * 128;
    const int wm = (wid >> 2) * 64, wn = (wid & 3) * 32;

    // per-thread cp.async mapping: 6 chunks of 16B (2 per buffer)
    uint32_t ldSm[6]; const fp16* ldG[6];
    #pragma unroll
    for (int i = 0; i < 6; i++) {
        const int buf = i >> 1;
        const int chunk = tid + (i & 1) * 256;       // 0..511
        const int r = chunk >> 2, j = chunk & 3;     // j: 16B unit (8 fp16)
        ldSm[i] = smb + buf * BUFB + r * ROWB + j * 16;
        const fp16* base = (buf == 0) ? Ahi : (buf == 1) ? Alo : Bh;
        const int rowg = (buf < 2) ? (bm + r) : (bn + r);
        ldG[i] = base + (size_t)rowg * K + j * 8;
    }

    const uint32_t aOff = (uint32_t)((wm + (lane & 15)) * ROWB + (((lane >> 4) << 3)) * 2);
    const uint32_t bOff = (uint32_t)((wn + ((lane >> 4) << 3) + (lane & 7)) * ROWB
                                     + ((((lane >> 3) & 1) << 3)) * 2);

    float acc[4][4][4] = {};
    const int NT = K / 32;

    #pragma unroll
    for (int i = 0; i < 6; i++) cp16(ldSm[i], ldG[i]);
    cp_commit();

    for (int t = 0; t < NT; t++) {
        if (t + 1 < NT) {
            const uint32_t so = ((t + 1) & 1) * STAGEB;
            const int kc = (t + 1) * 32;
            #pragma unroll
            for (int i = 0; i < 6; i++) cp16(ldSm[i] + so, ldG[i] + kc);
            cp_commit();
            cp_wait1();
        } else {
            cp_wait0();
        }
        __syncthreads();

        const uint32_t st = smb + (t & 1) * STAGEB;
        #pragma unroll
        for (int ks = 0; ks < 32; ks += 16) {
            uint32_t ah[4][4], al[4][4], bh2[2][4];
            #pragma unroll
            for (int mi = 0; mi < 4; mi++) {
                ldsm4(ah[mi], st + aOff + mi * (16 * ROWB) + ks * 2);
                ldsm4(al[mi], st + BUFB + aOff + mi * (16 * ROWB) + ks * 2);
            }
            #pragma unroll
            for (int n2 = 0; n2 < 2; n2++)
                ldsm4(bh2[n2], st + 2 * BUFB + bOff + n2 * (16 * ROWB) + ks * 2);
            #pragma unroll
            for (int mi = 0; mi < 4; mi++)
                #pragma unroll
                for (int ni = 0; ni < 4; ni++) {
                    const uint32_t* bp = &bh2[ni >> 1][(ni & 1) * 2];
                    mma16816(acc[mi][ni], ah[mi], bp);
                    mma16816(acc[mi][ni], al[mi], bp);
                }
        }
        __syncthreads();
    }

    // epilogue
    #pragma unroll
    for (int mi = 0; mi < 4; mi++)
        #pragma unroll
        for (int ni = 0; ni < 4; ni++) {
            #pragma unroll
            for (int half = 0; half < 2; half++) {
                const int r = bm + wm + mi * 16 + (lane >> 2) + half * 8;
                const int c = bn + wn + ni * 8 + (lane & 3) * 2;
                const size_t idx = (size_t)r * N + c;
                float d0 = acc[mi][ni][half * 2 + 0];
                float d1 = acc[mi][ni][half * 2 + 1];
                if (resid) {
                    const float2 q2 = *reinterpret_cast<const float2*>(&resid[idx]);
                    d0 += q2.x; d1 += q2.y;
                }
                if (Cf) *reinterpret_cast<float2*>(&Cf[idx]) = make_float2(d0, d1);
                if (Chi) {
                    __half2 h, l;
                    split_pair(d0, d1, &h, &l);
                    *reinterpret_cast<__half2*>(&Chi[idx]) = h;
                    if (Clo) *reinterpret_cast<__half2*>(&Clo[idx]) = l;
                }
            }
        }
}

// ------------------------- S = Q K^T (masked) --------------------------------
// per block: 128 q-rows x 128 k-cols, K=64, fp16 2-term.
// Staged smem epilogue for coalesced streaming writes.
#define ROWS_S 144                   // 64 fp16 (128B) + 16B pad
#define BUFS (128 * ROWS_S)          // 18432
#define SROW 132                     // fp32 stage row stride
#define SA_SMEM (128 * SROW * 4)     // 67584 >= 3*BUFS (55296)

__global__ __launch_bounds__(256, 1)
void sgemm_attn(const fp16* __restrict__ Ahi, const fp16* __restrict__ Alo,
                const fp16* __restrict__ Bh,
                const int* __restrict__ mask, float* __restrict__ attn)
{
    extern __shared__ __align__(128) char sb[];
    const uint32_t smb = smem_u32(sb);
    float* Ssm = reinterpret_cast<float*>(sb);
    const int tid = threadIdx.x, lane = tid & 31, wid = tid >> 5;
    const int k0t = blockIdx.x * 128;
    const int q0 = blockIdx.y * 128;
    const int bh = blockIdx.z;
    const int b = bh >> 4, h = bh & 15;
    const size_t hoff = (size_t)h * DK;
    const int wm = (wid >> 2) * 64, wn = (wid & 3) * 32;

    // load 3 buffers x 1024 chunks of 16B = 12/thread
    #pragma unroll
    for (int i = 0; i < 12; i++) {
        const int buf = i >> 2;
        const int chunk = tid + (i & 3) * 256;     // 0..1023
        const int r = chunk >> 3, j = chunk & 7;
        const fp16* base = (buf == 0) ? Ahi : (buf == 1) ? Alo : Bh;
        const int rowg = (buf < 2) ? (b * SS + q0 + r) : (b * SS + k0t + r);
        cp16(smb + buf * BUFS + r * ROWS_S + j * 16,
             base + (size_t)rowg * DM + hoff + j * 8);
    }
    cp_commit();

    const uint32_t aOff = (uint32_t)((wm + (lane & 15)) * ROWS_S + (((lane >> 4) << 3)) * 2);
    const uint32_t bOff = (uint32_t)((wn + ((lane >> 4) << 3) + (lane & 7)) * ROWS_S
                                     + ((((lane >> 3) & 1) << 3)) * 2);

    cp_wait0();
    __syncthreads();

    float acc[4][4][4] = {};
    #pragma unroll
    for (int ks = 0; ks < 64; ks += 16) {
        uint32_t ah[4][4], al[4][4], bh2[2][4];
        #pragma unroll
        for (int mi = 0; mi < 4; mi++) {
            ldsm4(ah[mi], smb + aOff + mi * (16 * ROWS_S) + ks * 2);
            ldsm4(al[mi], smb + BUFS + aOff + mi * (16 * ROWS_S) + ks * 2);
        }
        #pragma unroll
        for (int n2 = 0; n2 < 2; n2++)
            ldsm4(bh2[n2], smb + 2 * BUFS + bOff + n2 * (16 * ROWS_S) + ks * 2);
        #pragma unroll
        for (int mi = 0; mi < 4; mi++)
            #pragma unroll
            for (int ni = 0; ni < 4; ni++) {
                const uint32_t* bp = &bh2[ni >> 1][(ni & 1) * 2];
                mma16816(acc[mi][ni], ah[mi], bp);
                mma16816(acc[mi][ni], al[mi], bp);
            }
    }

    // stage S tile to smem (inputs fully consumed)
    __syncthreads();
    #pragma unroll
    for (int mi = 0; mi < 4; mi++)
        #pragma unroll
        for (int ni = 0; ni < 4; ni++) {
            #pragma unroll
            for (int half = 0; half < 2; half++) {
                const int r = wm + mi * 16 + (lane >> 2) + half * 8;
                const int c = wn + ni * 8 + (lane & 3) * 2;
                *reinterpret_cast<float2*>(&Ssm[r * SROW + c]) =
                    make_float2(acc[mi][ni][half * 2 + 0],
                                acc[mi][ni][half * 2 + 1]);
            }
        }
    __syncthreads();

    // coalesced streaming writes (+ mask if needed)
    const int allones = g_flag;
    #pragma unroll
    for (int p = 0; p < 16; p++) {
        const int chunk = tid + p * 256;            // 0..4095
        const int r = chunk >> 5, c4 = (chunk & 31) * 4;
        float4 v = *reinterpret_cast<const float4*>(&Ssm[r * SROW + c4]);
        const size_t grow = (size_t)(q0 + r);
        if (!allones) {
            const int4 m = *reinterpret_cast<const int4*>(
                &mask[((size_t)b * SS + grow) * SS + k0t + c4]);
            if (m.x == 0) v.x = -1e9f;
            if (m.y == 0) v.y = -1e9f;
            if (m.z == 0) v.z = -1e9f;
            if (m.w == 0) v.w = -1e9f;
        }
        __stcs(reinterpret_cast<float4*>(
                   &attn[((size_t)bh * SS + grow) * SS + k0t + c4]), v);
    }
}

// ------------------------- P = K^T V (64x64 per bh), split-K -----------------
__global__ __launch_bounds__(256)
void pk_kernel(const float* __restrict__ kh, const float* __restrict__ vh)
{
    if (g_flag == 0) return;
    __shared__ float Ks[32][68];
    __shared__ float Vs[32][68];
    const int bh = blockIdx.x, split = blockIdx.y;
    const int b = bh >> 4, h = bh & 15;
    const size_t hoff = (size_t)h * DK;
    const int tid = threadIdx.x;
    const int tx = tid & 15, ty = tid >> 4;
    float acc[4][4] = {};
    for (int it = 0; it < 8; it++) {
        const int s0 = split * 256 + it * 32;
        __syncthreads();
        #pragma unroll
        for (int t = 0; t < 2; t++) {
            const int idx = tid + t * 256;
            const int rr = idx >> 4, c4 = idx & 15;
            const size_t g = ((size_t)(b * SS + s0 + rr) * DM + hoff) / 4 + c4;
            *reinterpret_cast<float4*>(&Ks[rr][c4 * 4]) =
                reinterpret_cast<const float4*>(kh)[g];
            *reinterpret_cast<float4*>(&Vs[rr][c4 * 4]) =
                reinterpret_cast<const float4*>(vh)[g];
        }
        __syncthreads();
        #pragma unroll 4
        for (int s = 0; s < 32; s++) {
            const float4 vv = *reinterpret_cast<const float4*>(&Vs[s][tx * 4]);
            #pragma unroll
            for (int i = 0; i < 4; i++) {
                const float kv = Ks[s][ty * 4 + i];
                acc[i][0] += kv * vv.x; acc[i][1] += kv * vv.y;
                acc[i][2] += kv * vv.z; acc[i][3] += kv * vv.w;
            }
        }
    }
    #pragma unroll
    for (int i = 0; i < 4; i++)
        #pragma unroll
        for (int j = 0; j < 4; j++)
            atomicAdd(&g_P[bh * (DK * DK) + (ty * 4 + i) * DK + tx * 4 + j], acc[i][j]);
}

// ------------------------- O = Qs @ P (fast path) ----------------------------
__global__ __launch_bounds__(256)
void ofast_kernel(const float* __restrict__ qh)
{
    if (g_flag == 0) return;
    __shared__ float Qs[64][68];
    __shared__ float Ps[64][64];
    const int q0 = blockIdx.x * 64;
    const int bh = blockIdx.y;
    const int b = bh >> 4, h = bh & 15;
    const size_t hoff = (size_t)h * DK;
    const int tid = threadIdx.x;
    const int tx = tid & 15, ty = tid >> 4;
    #pragma unroll
    for (int t = 0; t < 4; t++) {
        const int idx = tid + t * 256;
        const int rr = idx >> 4, c4 = idx & 15;
        *reinterpret_cast<float4*>(&Qs[rr][c4 * 4]) =
            reinterpret_cast<const float4*>(qh)[((size_t)(b * SS + q0 + rr) * DM + hoff) / 4 + c4];
        *reinterpret_cast<float4*>(&Ps[rr][c4 * 4]) =
            reinterpret_cast<const float4*>(g_P)[(size_t)bh * (DK * DK) / 4 + rr * 16 + c4];
    }
    __syncthreads();
    float acc[4][4] = {};
    #pragma unroll 8
    for (int d = 0; d < 64; d++) {
        const float4 pv = *reinterpret_cast<const float4*>(&Ps[d][tx * 4]);
        #pragma unroll
        for (int i = 0; i < 4; i++) {
            const float qv = Qs[ty * 4 + i][d];
            acc[i][0] += qv * pv.x; acc[i][1] += qv * pv.y;
            acc[i][2] += qv * pv.z; acc[i][3] += qv * pv.w;
        }
    }
    #pragma unroll
    for (int i = 0; i < 4; i++) {
        const size_t base = (size_t)(b * SS + q0 + ty * 4 + i) * DM + hoff + tx * 4;
        __half2 h0, l0, h1, l1;
        split_pair(acc[i][0], acc[i][1], &h0, &l0);
        split_pair(acc[i][2], acc[i][3], &h1, &l1);
        __half2* ph = reinterpret_cast<__half2*>(&g_oh_hi[base]);
        __half2* pl = reinterpret_cast<__half2*>(&g_oh_lo[base]);
        ph[0] = h0; ph[1] = h1;
        pl[0] = l0; pl[1] = l1;
    }
}

// ------------------------- O = attn @ V (fallback) ---------------------------
__global__ __launch_bounds__(256)
void ofb_kernel(const float* __restrict__ attn, const float* __restrict__ vh)
{
    if (g_flag != 0) return;
    __shared__ float As[64][68];
    __shared__ float Vs[64][68];
    const int q0 = blockIdx.x * 64;
    const int bh = blockIdx.y;
    const int b = bh >> 4, h = bh & 15;
    const size_t hoff = (size_t)h * DK;
    const int tid = threadIdx.x;
    const int tx = tid & 15, ty = tid >> 4;
    float acc[4][4] = {};
    for (int k0 = 0; k0 < SS; k0 += 64) {
        __syncthreads();
        #pragma unroll
        for (int t = 0; t < 4; t++) {
            const int idx = tid + t * 256;
            const int rr = idx >> 4, c4 = idx & 15;
            *reinterpret_cast<float4*>(&As[rr][c4 * 4]) =
                reinterpret_cast<const float4*>(attn)[(((size_t)bh * SS + q0 + rr) * SS + k0) / 4 + c4];
            *reinterpret_cast<float4*>(&Vs[rr][c4 * 4]) =
                reinterpret_cast<const float4*>(vh)[((size_t)(b * SS + k0 + rr) * DM + hoff) / 4 + c4];
        }
        __syncthreads();
        #pragma unroll 8
        for (int kk = 0; kk < 64; kk++) {
            const float4 vv = *reinterpret_cast<const float4*>(&Vs[kk][tx * 4]);
            #pragma unroll
            for (int i = 0; i < 4; i++) {
                const float sv = As[ty * 4 + i][kk];
                acc[i][0] += sv * vv.x; acc[i][1] += sv * vv.y;
                acc[i][2] += sv * vv.z; acc[i][3] += sv * vv.w;
            }
        }
    }
    #pragma unroll
    for (int i = 0; i < 4; i++) {
        const size_t base = (size_t)(b * SS + q0 + ty * 4 + i) * DM + hoff + tx * 4;
        __half2 h0, l0, h1, l1;
        split_pair(acc[i][0], acc[i][1], &h0, &l0);
        split_pair(acc[i][2], acc[i][3], &h1, &l1);
        __half2* ph = reinterpret_cast<__half2*>(&g_oh_hi[base]);
        __half2* pl = reinterpret_cast<__half2*>(&g_oh_lo[base]);
        ph[0] = h0; ph[1] = h1;
        pl[0] = l0; pl[1] = l1;
    }
}

// ---------------------------------------------------------------------------
extern "C" void kernel_launch(void* const* d_in, const int* in_sizes, int n_in,
                              void* d_out, int out_size)
{
    const float* q     = (const float*)d_in[0];
    const float* k     = (const float*)d_in[1];
    const float* v     = (const float*)d_in[2];
    const int*   mask  = (const int*)  d_in[3];
    const float* Wq    = (const float*)d_in[4];
    const float* Wk    = (const float*)d_in[5];
    const float* Wv    = (const float*)d_in[6];
    const float* Wfc   = (const float*)d_in[7];
    const float* gamma = (const float*)d_in[8];
    const float* beta  = (const float*)d_in[9];
    float* out = (float*)d_out;
    float* attn = ((long long)out_size >= (long long)OUT_ELEMS + ATTN_ELEMS)
                      ? out + OUT_ELEMS : nullptr;

    void* p;
    #define SYM(T, name, sym) cudaGetSymbolAddress(&p, sym); T* name = (T*)p
    SYM(fp16, qn_hi, g_qn_hi); SYM(fp16, qn_lo, g_qn_lo);
    SYM(fp16, ki_hi, g_ki_hi); SYM(fp16, ki_lo, g_ki_lo);
    SYM(fp16, vi_hi, g_vi_hi); SYM(fp16, vi_lo, g_vi_lo);
    SYM(fp16, wq_hi, g_wq_hi);
    SYM(fp16, wk_hi, g_wk_hi);
    SYM(fp16, wv_hi, g_wv_hi);
    SYM(fp16, wf_hi, g_wf_hi);
    SYM(float, qh, g_qh); SYM(fp16, qh_hi, g_qh_hi); SYM(fp16, qh_lo, g_qh_lo);
    SYM(float, kh, g_kh); SYM(fp16, kh_hi, g_kh_hi);
    SYM(float, vh, g_vh);
    SYM(fp16, oh_hi, g_oh_hi); SYM(fp16, oh_lo, g_oh_lo);
    #undef SYM

    cudaFuncSetAttribute(tgemm, cudaFuncAttributeMaxDynamicSharedMemorySize, TG_SMEM);
    cudaFuncSetAttribute(sgemm_attn, cudaFuncAttributeMaxDynamicSharedMemorySize, SA_SMEM);

    // prep
    initk<<<512, 256>>>();
    maskchk<<<2048, 256>>>(mask);
    ln_kernel<<<NROWS, 256>>>(q, gamma, beta, qn_hi, qn_lo);
    splitk<<<NROWS * DM / 4 / 256, 256>>>(k, ki_hi, ki_lo, NROWS * DM / 4);
    splitk<<<NROWS * DM / 4 / 256, 256>>>(v, vi_hi, vi_lo, NROWS * DM / 4);
    dim3 wg(32, 32), wb(32, 8);
    wprep<<<wg, wb>>>(Wq, wq_hi);
    wprep<<<wg, wb>>>(Wk, wk_hi);
    wprep<<<wg, wb>>>(Wv, wv_hi);
    wprep<<<wg, wb>>>(Wfc, wf_hi);

    // projections (fp16 2-term mma.sync)
    dim3 gg(DM / 128, NROWS / 128);
    tgemm<<<gg, 256, TG_SMEM>>>(qn_hi, qn_lo, wq_hi,
                                qh, qh_hi, qh_lo, nullptr, DM, DM);
    tgemm<<<gg, 256, TG_SMEM>>>(ki_hi, ki_lo, wk_hi,
                                kh, kh_hi, nullptr, nullptr, DM, DM);
    tgemm<<<gg, 256, TG_SMEM>>>(vi_hi, vi_lo, wv_hi,
                                vh, nullptr, nullptr, nullptr, DM, DM);

    // attn scores + mask
    if (attn)
        sgemm_attn<<<dim3(SS / 128, SS / 128, BB * NH), 256, SA_SMEM>>>(
            qh_hi, qh_lo, kh_hi, mask, attn);

    // O: fast path (mask all-ones) or fallback
    pk_kernel<<<dim3(BB * NH, 8), 256>>>(kh, vh);
    ofast_kernel<<<dim3(SS / 64, BB * NH), 256>>>(qh);
    if (attn)
        ofb_kernel<<<dim3(SS / 64, BB * NH), 256>>>(attn, vh);

    // fc + residual
    tgemm<<<gg, 256, TG_SMEM>>>(oh_hi, oh_lo, wf_hi,
                                out, nullptr, nullptr, q, DM, DM);
}